// round 3
// baseline (speedup 1.0000x reference)
#include <cuda_runtime.h>
#include <cuda_bf16.h>

#define NB 4
#define NC 128
#define HWP (512*512)
#define NL 512
#define TILE 2048
#define THREADS 256

__device__ int g_counts[NB * NL];
__device__ int g_lab64;   // 1 if labels are int64, 0 if int32

__device__ __forceinline__ void red4(float* p, float a, float b, float c, float d) {
    asm volatile("red.global.add.v4.f32 [%0], {%1,%2,%3,%4};"
                 :: "l"(p), "f"(a), "f"(b), "f"(c), "f"(d) : "memory");
}

// Probe label dtype: int64-LE labels in [0,512) have all odd 32-bit words == 0.
// For int32 labels, P(128 consecutive odd words all zero) ~ 512^-128 ~ 0.
__global__ void detect_kernel(const unsigned int* __restrict__ lab32) {
    int is64 = 1;
    for (int i = 0; i < 128; i++) {
        if (lab32[2 * i + 1] != 0u || lab32[2 * i] >= 512u) { is64 = 0; break; }
    }
    g_lab64 = is64;
}

__global__ void zero_kernel(float* __restrict__ out) {
    int i = blockIdx.x * 256 + threadIdx.x;
    if (i < NB * NL * NC) out[i] = 0.0f;
    if (i < NB * NL) g_counts[i] = 0;
}

__global__ __launch_bounds__(THREADS) void accum_kernel(
    const float* __restrict__ x,
    const void* __restrict__ lab_raw,
    float* __restrict__ out)
{
    __shared__ int slab[TILE];
    __shared__ int hist[NL];

    const int b   = blockIdx.y;
    const int p0  = blockIdx.x * TILE;
    const int tid = threadIdx.x;

    for (int i = tid; i < NL; i += THREADS) hist[i] = 0;
    __syncthreads();

    const int lab64 = g_lab64;
    if (lab64) {
        const long long* lb = (const long long*)lab_raw + (size_t)b * HWP + p0;
        for (int i = tid; i < TILE; i += THREADS) {
            int l = ((int)lb[i]) & (NL - 1);
            slab[i] = l;
            atomicAdd(&hist[l], 1);
        }
    } else {
        const int* lb = (const int*)lab_raw + (size_t)b * HWP + p0;
        for (int i = tid; i < TILE; i += THREADS) {
            int l = lb[i] & (NL - 1);
            slab[i] = l;
            atomicAdd(&hist[l], 1);
        }
    }
    __syncthreads();

    for (int i = tid; i < NL; i += THREADS) {
        int h = hist[i];
        if (h) atomicAdd(&g_counts[b * NL + i], h);
    }

    const float* xb = x + (size_t)b * NC * HWP + p0;
    float*       ob = out + (size_t)b * NL * NC;

    #pragma unroll 1
    for (int cg = 0; cg < NC / 4; cg++) {
        const float* x0 = xb + (size_t)(4 * cg) * HWP;
        #pragma unroll 1
        for (int i = 4 * tid; i < TILE; i += 4 * THREADS) {
            float4 a0 = *(const float4*)(x0 + i);
            float4 a1 = *(const float4*)(x0 + (size_t)HWP + i);
            float4 a2 = *(const float4*)(x0 + (size_t)2 * HWP + i);
            float4 a3 = *(const float4*)(x0 + (size_t)3 * HWP + i);
            int l0 = slab[i], l1 = slab[i + 1], l2 = slab[i + 2], l3 = slab[i + 3];
            red4(ob + l0 * NC + 4 * cg, a0.x, a1.x, a2.x, a3.x);
            red4(ob + l1 * NC + 4 * cg, a0.y, a1.y, a2.y, a3.y);
            red4(ob + l2 * NC + 4 * cg, a0.z, a1.z, a2.z, a3.z);
            red4(ob + l3 * NC + 4 * cg, a0.w, a1.w, a2.w, a3.w);
        }
    }
}

__global__ void finalize_kernel(float* __restrict__ out) {
    int i = blockIdx.x * 256 + threadIdx.x;
    if (i >= NB * NL * NC) return;
    int bl = i / NC;
    int c = g_counts[bl];
    float cnt = (float)(c > 1 ? c : 1);
    out[i] = out[i] / cnt;
}

extern "C" void kernel_launch(void* const* d_in, const int* in_sizes, int n_in,
                              void* d_out, int out_size) {
    // Resolve input binding by element count — x has 134217728 elements,
    // label_maps has 1048576. Do not trust ordering.
    const float* x;
    const void*  lab;
    if (in_sizes[0] > in_sizes[1]) {
        x   = (const float*)d_in[0];
        lab = d_in[1];
    } else {
        x   = (const float*)d_in[1];
        lab = d_in[0];
    }
    float* out = (float*)d_out;

    detect_kernel<<<1, 1>>>((const unsigned int*)lab);

    int ztot = NB * NL * NC;  // 262144 (covers both out and counts ranges)
    zero_kernel<<<(ztot + 255) / 256, 256>>>(out);

    dim3 grid(HWP / TILE, NB);  // 128 x 4 = 512 CTAs
    accum_kernel<<<grid, THREADS>>>(x, lab, out);

    finalize_kernel<<<(ztot + 255) / 256, 256>>>(out);
}

// round 4
// speedup vs baseline: 1.4162x; 1.4162x over previous
#include <cuda_runtime.h>
#include <cuda_bf16.h>

#define NB 4
#define NC 128
#define HWP (512*512)
#define NL 512
#define TILE 8192
#define THREADS 512

// dynamic smem layout (bytes)
#define OFF_SX     0                         // float sx[4][TILE]        = 131072
#define OFF_SLAB   131072                    // ushort slab[TILE]        = 16384
#define OFF_SIDX   147456                    // ushort sidx[TILE]        = 16384
#define OFF_CNT    163840                    // int cnt[NL]              = 2048
#define OFF_START  165888                    // int start[NL]            = 2048
#define OFF_CURSOR 167936                    // int cursor[NL]           = 2048
#define OFF_WSUM   169984                    // int wsum[16]             = 64
#define SMEM_BYTES 170112

__device__ int g_counts[NB * NL];
__device__ int g_lab64;   // 1 if labels are int64, 0 if int32

__device__ __forceinline__ void red4(float* p, float a, float b, float c, float d) {
    asm volatile("red.global.add.v4.f32 [%0], {%1,%2,%3,%4};"
                 :: "l"(p), "f"(a), "f"(b), "f"(c), "f"(d) : "memory");
}

// Probe label dtype: int64-LE labels in [0,512) have all odd 32-bit words == 0.
__global__ void detect_kernel(const unsigned int* __restrict__ lab32) {
    int is64 = 1;
    for (int i = 0; i < 128; i++) {
        if (lab32[2 * i + 1] != 0u || lab32[2 * i] >= 512u) { is64 = 0; break; }
    }
    g_lab64 = is64;
}

__global__ void zero_kernel(float* __restrict__ out) {
    int i = blockIdx.x * 256 + threadIdx.x;
    if (i < NB * NL * NC) out[i] = 0.0f;
    if (i < NB * NL) g_counts[i] = 0;
}

__global__ __launch_bounds__(THREADS) void accum_kernel(
    const float* __restrict__ x,
    const void* __restrict__ lab_raw,
    float* __restrict__ out)
{
    extern __shared__ char smem[];
    float*          sx     = (float*)(smem + OFF_SX);
    unsigned short* slab   = (unsigned short*)(smem + OFF_SLAB);
    unsigned short* sidx   = (unsigned short*)(smem + OFF_SIDX);
    int*            cnt    = (int*)(smem + OFF_CNT);
    int*            start  = (int*)(smem + OFF_START);
    int*            cursor = (int*)(smem + OFF_CURSOR);
    int*            wsum   = (int*)(smem + OFF_WSUM);

    const int b    = blockIdx.y;
    const int p0   = blockIdx.x * TILE;
    const int tid  = threadIdx.x;
    const int lane = tid & 31;
    const int wid  = tid >> 5;

    cnt[tid] = 0;   // THREADS == NL: one entry per thread
    __syncthreads();

    // ---- load labels, build histogram ----
    if (g_lab64) {
        const long long* lb = (const long long*)lab_raw + (size_t)b * HWP + p0;
        for (int i = tid; i < TILE; i += THREADS) {
            int l = ((int)lb[i]) & (NL - 1);
            slab[i] = (unsigned short)l;
            atomicAdd(&cnt[l], 1);
        }
    } else {
        const int* lb = (const int*)lab_raw + (size_t)b * HWP + p0;
        for (int i = tid; i < TILE; i += THREADS) {
            int l = lb[i] & (NL - 1);
            slab[i] = (unsigned short)l;
            atomicAdd(&cnt[l], 1);
        }
    }
    __syncthreads();

    // ---- exclusive prefix sum over cnt[512] (one element per thread) ----
    int v = cnt[tid];
    int s = v;
    #pragma unroll
    for (int d = 1; d < 32; d <<= 1) {
        int n = __shfl_up_sync(0xffffffffu, s, d);
        if (lane >= d) s += n;
    }
    if (lane == 31) wsum[wid] = s;
    __syncthreads();
    if (tid < 16) {
        int t = wsum[tid];
        #pragma unroll
        for (int d = 1; d < 16; d <<= 1) {
            int n = __shfl_up_sync(0x0000ffffu, t, d);
            if ((int)tid >= d) t += n;
        }
        wsum[tid] = t;
    }
    __syncthreads();
    int excl = s - v + (wid ? wsum[wid - 1] : 0);
    start[tid]  = excl;
    cursor[tid] = excl;
    if (v) atomicAdd(&g_counts[b * NL + tid], v);
    __syncthreads();

    // ---- scatter: sorted pixel indices by label ----
    for (int i = tid; i < TILE; i += THREADS) {
        int l = slab[i];
        int pos = atomicAdd(&cursor[l], 1);
        sidx[pos] = (unsigned short)i;
    }
    __syncthreads();

    // ---- per 4-channel group: stage coalesced, gather sorted, one red per label ----
    const float* xb = x + (size_t)b * NC * HWP + p0;
    float*       ob = out + (size_t)b * NL * NC;
    const int n    = cnt[tid];     // this thread's label run length
    const int base = start[tid];

    #pragma unroll 1
    for (int cg = 0; cg < NC / 4; cg++) {
        const float* xp = xb + (size_t)(4 * cg) * HWP;
        #pragma unroll
        for (int c = 0; c < 4; c++) {
            const float* src = xp + (size_t)c * HWP;
            float*       dst = sx + c * TILE;
            #pragma unroll
            for (int i = 4 * tid; i < TILE; i += 4 * THREADS)
                *(float4*)(dst + i) = *(const float4*)(src + i);
        }
        __syncthreads();

        float a0 = 0.f, a1 = 0.f, a2 = 0.f, a3 = 0.f;
        #pragma unroll 1
        for (int j = 0; j < n; j++) {
            int i2 = sidx[base + j];
            a0 += sx[i2];
            a1 += sx[TILE + i2];
            a2 += sx[2 * TILE + i2];
            a3 += sx[3 * TILE + i2];
        }
        if (n) red4(ob + tid * NC + 4 * cg, a0, a1, a2, a3);
        __syncthreads();
    }
}

__global__ void finalize_kernel(float* __restrict__ out) {
    int i = blockIdx.x * 256 + threadIdx.x;
    if (i >= NB * NL * NC) return;
    int bl = i / NC;
    int c = g_counts[bl];
    float cnt = (float)(c > 1 ? c : 1);
    out[i] = out[i] / cnt;
}

extern "C" void kernel_launch(void* const* d_in, const int* in_sizes, int n_in,
                              void* d_out, int out_size) {
    // Resolve input binding by element count — x has 134217728 elements,
    // label_maps has 1048576. Do not trust ordering.
    const float* x;
    const void*  lab;
    if (in_sizes[0] > in_sizes[1]) {
        x   = (const float*)d_in[0];
        lab = d_in[1];
    } else {
        x   = (const float*)d_in[1];
        lab = d_in[0];
    }
    float* out = (float*)d_out;

    cudaFuncSetAttribute(accum_kernel,
                         cudaFuncAttributeMaxDynamicSharedMemorySize, SMEM_BYTES);

    detect_kernel<<<1, 1>>>((const unsigned int*)lab);

    int ztot = NB * NL * NC;  // 262144 (covers both out and counts ranges)
    zero_kernel<<<(ztot + 255) / 256, 256>>>(out);

    dim3 grid(HWP / TILE, NB);  // 32 x 4 = 128 CTAs
    accum_kernel<<<grid, THREADS, SMEM_BYTES>>>(x, lab, out);

    finalize_kernel<<<(ztot + 255) / 256, 256>>>(out);
}

// round 5
// speedup vs baseline: 1.4262x; 1.0071x over previous
#include <cuda_runtime.h>
#include <cuda_bf16.h>

#define NB 4
#define NC 128
#define HWP (512*512)
#define NL 512
#define TILE 4096
#define THREADS 512
#define PLANE  TILE                 // floats per channel plane
#define PLANEB (TILE * 4)           // bytes per plane

// dynamic smem layout (bytes)
#define OFF_SX     0                // float sx[2][TILE]   = 32768
#define OFF_SLAB   32768            // ushort slab[TILE]   = 8192
#define OFF_SIDX   40960            // ushort sidx[TILE]   = 8192
#define OFF_CNT    49152            // int cnt[NL]         = 2048
#define OFF_START  51200            // int start[NL]       = 2048
#define OFF_CURSOR 53248            // int cursor[NL]      = 2048
#define OFF_WSUM   55296            // int wsum[16]        = 64
#define SMEM_BYTES 55360

__device__ int g_counts[NB * NL];
__device__ int g_lab64;   // 1 if labels are int64, 0 if int32

__device__ __forceinline__ void red4(float* p, float a, float b, float c, float d) {
    asm volatile("red.global.add.v4.f32 [%0], {%1,%2,%3,%4};"
                 :: "l"(p), "f"(a), "f"(b), "f"(c), "f"(d) : "memory");
}

__device__ __forceinline__ void cpasync16(unsigned int s, const void* g) {
    asm volatile("cp.async.cg.shared.global [%0], [%1], 16;" :: "r"(s), "l"(g));
}

// copy one channel plane (TILE floats) to smem buffer, async
__device__ __forceinline__ void issue_channel(unsigned int sbuf, const float* src, int tid) {
    cpasync16(sbuf + tid * 16,              src + 4 * tid);
    cpasync16(sbuf + (tid + THREADS) * 16,  src + 4 * (tid + THREADS));
}

// Probe label dtype: int64-LE labels in [0,512) have all odd 32-bit words == 0.
__global__ void detect_kernel(const unsigned int* __restrict__ lab32) {
    int is64 = 1;
    for (int i = 0; i < 128; i++) {
        if (lab32[2 * i + 1] != 0u || lab32[2 * i] >= 512u) { is64 = 0; break; }
    }
    g_lab64 = is64;
}

__global__ void zero_kernel(float* __restrict__ out) {
    int i = blockIdx.x * 256 + threadIdx.x;
    if (i < NB * NL * NC) out[i] = 0.0f;
    if (i < NB * NL) g_counts[i] = 0;
}

__global__ __launch_bounds__(THREADS, 4) void accum_kernel(
    const float* __restrict__ x,
    const void* __restrict__ lab_raw,
    float* __restrict__ out)
{
    extern __shared__ char smem[];
    unsigned short* slab   = (unsigned short*)(smem + OFF_SLAB);
    unsigned short* sidx   = (unsigned short*)(smem + OFF_SIDX);
    int*            cnt    = (int*)(smem + OFF_CNT);
    int*            start  = (int*)(smem + OFF_START);
    int*            cursor = (int*)(smem + OFF_CURSOR);
    int*            wsum   = (int*)(smem + OFF_WSUM);

    const int b    = blockIdx.y;
    const int p0   = blockIdx.x * TILE;
    const int tid  = threadIdx.x;
    const int lane = tid & 31;
    const int wid  = tid >> 5;

    unsigned int smem_u32 = (unsigned int)__cvta_generic_to_shared(smem);
    const float* xb = x + (size_t)b * NC * HWP + p0;

    // Prefetch channel 0 immediately — hides the sort prologue under DRAM.
    issue_channel(smem_u32 + OFF_SX, xb, tid);
    asm volatile("cp.async.commit_group;");

    cnt[tid] = 0;   // THREADS == NL
    __syncthreads();

    // ---- load labels, build histogram ----
    if (g_lab64) {
        const long long* lb = (const long long*)lab_raw + (size_t)b * HWP + p0;
        for (int i = tid; i < TILE; i += THREADS) {
            int l = ((int)lb[i]) & (NL - 1);
            slab[i] = (unsigned short)l;
            atomicAdd(&cnt[l], 1);
        }
    } else {
        const int* lb = (const int*)lab_raw + (size_t)b * HWP + p0;
        for (int i = tid; i < TILE; i += THREADS) {
            int l = lb[i] & (NL - 1);
            slab[i] = (unsigned short)l;
            atomicAdd(&cnt[l], 1);
        }
    }
    __syncthreads();

    // ---- exclusive prefix sum over cnt[512] ----
    int v = cnt[tid];
    int s = v;
    #pragma unroll
    for (int d = 1; d < 32; d <<= 1) {
        int n2 = __shfl_up_sync(0xffffffffu, s, d);
        if (lane >= d) s += n2;
    }
    if (lane == 31) wsum[wid] = s;
    __syncthreads();
    if (tid < 16) {
        int t = wsum[tid];
        #pragma unroll
        for (int d = 1; d < 16; d <<= 1) {
            int n2 = __shfl_up_sync(0x0000ffffu, t, d);
            if ((int)tid >= d) t += n2;
        }
        wsum[tid] = t;
    }
    __syncthreads();
    int excl = s - v + (wid ? wsum[wid - 1] : 0);
    start[tid]  = excl;
    cursor[tid] = excl;
    if (v) atomicAdd(&g_counts[b * NL + tid], v);
    __syncthreads();

    // ---- scatter: sorted pixel indices by label ----
    for (int i = tid; i < TILE; i += THREADS) {
        int l = slab[i];
        int pos = atomicAdd(&cursor[l], 1);
        sidx[pos] = (unsigned short)i;
    }
    __syncthreads();

    // ---- pipelined per-channel gather ----
    float* ob = out + (size_t)b * NL * NC;
    const int n    = cnt[tid];
    const unsigned short* sp = sidx + start[tid];

    int cur = 0;
    #pragma unroll 1
    for (int cg = 0; cg < NC / 4; cg++) {
        float acc[4];
        #pragma unroll
        for (int cc = 0; cc < 4; cc++) {
            const int c = 4 * cg + cc;
            if (c + 1 < NC) {
                issue_channel(smem_u32 + OFF_SX + (cur ^ 1) * PLANEB,
                              xb + (size_t)(c + 1) * HWP, tid);
                asm volatile("cp.async.commit_group;");
                asm volatile("cp.async.wait_group 1;");
            } else {
                asm volatile("cp.async.wait_group 0;");
            }
            __syncthreads();   // buf[cur] fully landed for all warps

            const float* buf = (const float*)(smem + OFF_SX + cur * PLANEB);
            float a = 0.f;
            #pragma unroll 1
            for (int j = 0; j < n; j++) a += buf[sp[j]];
            acc[cc] = a;

            __syncthreads();   // all warps done with buf[cur] before it is re-filled
            cur ^= 1;
        }
        if (n) red4(ob + tid * NC + 4 * cg, acc[0], acc[1], acc[2], acc[3]);
    }
}

__global__ void finalize_kernel(float* __restrict__ out) {
    int i = blockIdx.x * 256 + threadIdx.x;
    if (i >= NB * NL * NC) return;
    int bl = i / NC;
    int c = g_counts[bl];
    float cnt = (float)(c > 1 ? c : 1);
    out[i] = out[i] / cnt;
}

extern "C" void kernel_launch(void* const* d_in, const int* in_sizes, int n_in,
                              void* d_out, int out_size) {
    // Resolve input binding by element count — x has 134217728 elements,
    // label_maps has 1048576. Do not trust ordering.
    const float* x;
    const void*  lab;
    if (in_sizes[0] > in_sizes[1]) {
        x   = (const float*)d_in[0];
        lab = d_in[1];
    } else {
        x   = (const float*)d_in[1];
        lab = d_in[0];
    }
    float* out = (float*)d_out;

    cudaFuncSetAttribute(accum_kernel,
                         cudaFuncAttributeMaxDynamicSharedMemorySize, SMEM_BYTES);

    detect_kernel<<<1, 1>>>((const unsigned int*)lab);

    int ztot = NB * NL * NC;  // 262144
    zero_kernel<<<(ztot + 255) / 256, 256>>>(out);

    dim3 grid(HWP / TILE, NB);  // 64 x 4 = 256 CTAs, fully resident
    accum_kernel<<<grid, THREADS, SMEM_BYTES>>>(x, lab, out);

    finalize_kernel<<<(ztot + 255) / 256, 256>>>(out);
}